// round 14
// baseline (speedup 1.0000x reference)
#include <cuda_runtime.h>

#define B_DIM 128
#define N_DIM 8192
#define HW    49
#define ROW_STRIDE_Q4 100352   // 8192*49/4 : float4 stride between rows of x

typedef unsigned long long u64;
typedef unsigned int u32;

__device__ __forceinline__ u64 pk2(float lo, float hi) {
    u64 r; asm("mov.b64 %0, {%1,%2};" : "=l"(r) : "f"(lo), "f"(hi)); return r;
}
__device__ __forceinline__ void upk2(u64 v, float& lo, float& hi) {
    asm("mov.b64 {%0,%1}, %2;" : "=f"(lo), "=f"(hi) : "l"(v));
}
__device__ __forceinline__ u64 fma2(u64 a, u64 b, u64 c) {
    u64 d; asm("fma.rn.f32x2 %0, %1, %2, %3;" : "=l"(d) : "l"(a), "l"(b), "l"(c)); return d;
}
__device__ __forceinline__ u64 add2(u64 a, u64 b) {
    u64 d; asm("add.rn.f32x2 %0, %1, %2;" : "=l"(d) : "l"(a), "l"(b)); return d;
}
__device__ __forceinline__ float ex2f(float x) {
    float y; asm("ex2.approx.ftz.f32 %0, %1;" : "=f"(y) : "f"(x)); return y;
}
// two scalar f32 scores -> one f16x2 -> one MUFU for two exps
__device__ __forceinline__ u32 ex2h2s(float slo, float shi) {
    u32 h; asm("cvt.rn.f16x2.f32 %0, %1, %2;" : "=r"(h) : "f"(shi), "f"(slo));
    u32 e; asm("ex2.approx.f16x2 %0, %1;" : "=r"(e) : "r"(h));
    return e;
}

__global__ __launch_bounds__(128, 16) void rsca_kernel(
    const float* __restrict__ x, const float* __restrict__ y,
    const float* __restrict__ swq, const float* __restrict__ swk,
    const float* __restrict__ swv, const float* __restrict__ sbq,
    const float* __restrict__ sbk, const float* __restrict__ sbv,
    const float* __restrict__ swo, const float* __restrict__ sbo,
    float* __restrict__ out)
{
    const int n = blockIdx.x;
    const int i = threadIdx.x;
    const int lane = i & 31;
    const int w = i >> 5;
    const int half = lane >> 4;        // 0 or 1 : which row of the pair
    const int sl = lane & 15;          // sub-lane within the 16-lane segment

    __shared__ float rows_s[B_DIM];    // 512 B : pooled row sums
    __shared__ float4 kv[B_DIM];       // 2 KB  : {kx, ky, vx, vy}
    __shared__ float4 wred[4];

    const float wq = *swq, wk = *swk, wv = *swv;
    const float bq = *sbq, bk = *sbk, bv = *sbv;
    const float wo = *swo, bo = *sbo;

    // ---- Warp-cooperative COALESCED pooling ----
    // Row r window: floats [n*49 - a, n*49 - a + 52) of row r, 16B-aligned start.
    // One LDG.128: lanes 0-12 load row A's 13 quads (208 contiguous bytes),
    // lanes 16-28 row B's. ~4-5 L1 wavefronts/instr vs 32 for the direct scheme.
    const int a = n & 3;
    const size_t baseq = ((size_t)n * HW - a) >> 2;   // float4 offset, exact
    const float4* g4 = (const float4*)x + baseq;

    #pragma unroll 4
    for (int t = 0; t < 16; ++t) {
        const int row = (w * 16 + t) * 2 + half;      // 0..127, each once
        float v = 0.f;
        if (sl < 13) {
            const float4 qd = g4[(size_t)row * ROW_STRIDE_Q4 + sl];
            v = (qd.x + qd.y) + (qd.z + qd.w);
            if (sl == 0) {                 // remove invalid head w0..w(a-1)
                if (a >= 1) v -= qd.x;
                if (a >= 2) v -= qd.y;
                if (a >= 3) v -= qd.z;
            }
            if (sl == 12) {                // remove invalid tail w(49+a)..w51
                if (a < 1) v -= qd.y;
                if (a < 2) v -= qd.z;
                if (a < 3) v -= qd.w;
            }
        }
        // segmented (width=16) tree sum: lane 0 / lane 16 hold row sums
        v += __shfl_down_sync(0xFFFFFFFFu, v, 8, 16);
        v += __shfl_down_sync(0xFFFFFFFFu, v, 4, 16);
        v += __shfl_down_sync(0xFFFFFFFFu, v, 2, 16);
        v += __shfl_down_sync(0xFFFFFFFFu, v, 1, 16);
        if (sl == 0) rows_s[row] = v;
    }
    __syncthreads();

    const float ax = rows_s[i] * (1.0f / 49.0f);
    const float ay = y[(size_t)i * N_DIM + (size_t)n];

    // ---- projections (k pre-scaled by log2 e) ----
    const float L2E = 1.4426950408889634f;
    const float qx = fmaf(ax, wq, bq);
    const float qy = fmaf(ay, wq, bq);
    const float kx = fmaf(ax, wk, bk) * L2E;
    const float ky = fmaf(ay, wk, bk) * L2E;
    const float vx = fmaf(ax, wv, bv);
    const float vy = fmaf(ay, wv, bv);

    kv[i] = make_float4(kx, ky, vx, vy);

    // ---- block min/max of kx, ky (analytic per-row softmax max) ----
    float kxmx = kx, kxmn = kx, kymx = ky, kymn = ky;
    #pragma unroll
    for (int off = 16; off; off >>= 1) {
        kxmx = fmaxf(kxmx, __shfl_xor_sync(0xFFFFFFFFu, kxmx, off));
        kxmn = fminf(kxmn, __shfl_xor_sync(0xFFFFFFFFu, kxmn, off));
        kymx = fmaxf(kymx, __shfl_xor_sync(0xFFFFFFFFu, kymx, off));
        kymn = fminf(kymn, __shfl_xor_sync(0xFFFFFFFFu, kymn, off));
    }
    if (lane == 0) wred[w] = make_float4(kxmx, kxmn, kymx, kymn);
    __syncthreads();
    {
        float4 r0 = wred[0], r1 = wred[1], r2 = wred[2], r3 = wred[3];
        kxmx = fmaxf(fmaxf(r0.x, r1.x), fmaxf(r2.x, r3.x));
        kxmn = fminf(fminf(r0.y, r1.y), fminf(r2.y, r3.y));
        kymx = fmaxf(fmaxf(r0.z, r1.z), fmaxf(r2.z, r3.z));
        kymn = fminf(fminf(r0.w, r1.w), fminf(r2.w, r3.w));
    }

    const float nm1 = -((qx >= 0.f) ? qx * kxmx : qx * kxmn);  // self_x : qx,kx
    const float nm2 = -((qy >= 0.f) ? qy * kymx : qy * kymn);  // self_y : qy,ky
    const float nm3 = -((qx >= 0.f) ? qx * kymx : qx * kymn);  // cross_x: qx,ky
    const float nm4 = -((qy >= 0.f) ? qy * kxmx : qy * kxmn);  // cross_y: qy,kx

    // ---- fused 4-combo attention, scalar idiom, 3 MUFU/j ----
    float d1 = 0.f, n1 = 0.f, d2 = 0.f, n2 = 0.f;
    u64 d43 = 0, n43 = 0;                 // packed {c4, c3} accumulators

    #pragma unroll 8
    for (int j = 0; j < B_DIM; ++j) {
        const float4 p = kv[j];           // {kx, ky, vx, vy} via broadcast LDS.128

        const float s1 = fmaf(qx, p.x, nm1);
        const float s2 = fmaf(qy, p.y, nm2);
        const float s4 = fmaf(qy, p.x, nm4);
        const float s3 = fmaf(qx, p.y, nm3);

        const float e1 = ex2f(s1);
        const float e2 = ex2f(s2);
        const u32 eh = ex2h2s(s4, s3);    // f16x2 {2^s4, 2^s3}

        // exact unpack, scaled 2^-112 (cancels in n/d); masks load-bearing
        const u32 lo = (eh << 13) & 0x0FFFE000u;
        const u32 hi = (eh >> 3)  & 0x0FFFE000u;
        const u64 f43 = pk2(__uint_as_float(lo), __uint_as_float(hi));

        d1 += e1; n1 = fmaf(e1, p.z, n1);
        d2 += e2; n2 = fmaf(e2, p.w, n2);
        const u64 vp = pk2(p.z, p.w);     // aligned pair from LDS.128
        d43 = add2(d43, f43);
        n43 = fma2(f43, vp, n43);          // n4+=e4*vx, n3+=e3*vy
    }

    float nn4, nn3, dd4, dd3;
    upk2(n43, nn4, nn3); upk2(d43, dd4, dd3);

    const float osx = __fdividef(n1, d1);
    const float osy = __fdividef(n2, d2);
    const float ocx = __fdividef(nn3, dd3);   // 2^-112 scale cancels
    const float ocy = __fdividef(nn4, dd4);

    const float ox = fmaf(wo, osx + ocx, ax + 2.0f * bo);
    const float oy = fmaf(wo, osy + ocy, ay + 2.0f * bo);

    out[(size_t)i * (2 * N_DIM) + (size_t)n]         = ox;
    out[(size_t)i * (2 * N_DIM) + N_DIM + (size_t)n] = oy;
}

extern "C" void kernel_launch(void* const* d_in, const int* in_sizes, int n_in,
                              void* d_out, int out_size) {
    const float* x   = (const float*)d_in[0];
    const float* y   = (const float*)d_in[1];
    const float* swq = (const float*)d_in[2];
    const float* swk = (const float*)d_in[3];
    const float* swv = (const float*)d_in[4];
    const float* sbq = (const float*)d_in[5];
    const float* sbk = (const float*)d_in[6];
    const float* sbv = (const float*)d_in[7];
    const float* swo = (const float*)d_in[8];
    const float* sbo = (const float*)d_in[9];
    float* out = (float*)d_out;

    rsca_kernel<<<N_DIM, B_DIM>>>(x, y, swq, swk, swv, sbq, sbk, sbv, swo, sbo, out);
}

// round 15
// speedup vs baseline: 1.1474x; 1.1474x over previous
#include <cuda_runtime.h>

#define B_DIM 128
#define N_DIM 8192
#define HW    49
#define ROWQ  13               // float4 quads per row window (52 floats)
#define PASS_ROWS 32
#define PASS_QUADS (PASS_ROWS * ROWQ)   // 416 quads staged per pass (6656 B)
#define ROW_STRIDE_Q4 100352   // 8192*49/4 : float4 stride between rows of x

typedef unsigned long long u64;
typedef unsigned int u32;

__device__ __forceinline__ u64 pk2(float lo, float hi) {
    u64 r; asm("mov.b64 %0, {%1,%2};" : "=l"(r) : "f"(lo), "f"(hi)); return r;
}
__device__ __forceinline__ void upk2(u64 v, float& lo, float& hi) {
    asm("mov.b64 {%0,%1}, %2;" : "=f"(lo), "=f"(hi) : "l"(v));
}
__device__ __forceinline__ u64 fma2(u64 a, u64 b, u64 c) {
    u64 d; asm("fma.rn.f32x2 %0, %1, %2, %3;" : "=l"(d) : "l"(a), "l"(b), "l"(c)); return d;
}
__device__ __forceinline__ u64 add2(u64 a, u64 b) {
    u64 d; asm("add.rn.f32x2 %0, %1, %2;" : "=l"(d) : "l"(a), "l"(b)); return d;
}
__device__ __forceinline__ float ex2f(float x) {
    float y; asm("ex2.approx.ftz.f32 %0, %1;" : "=f"(y) : "f"(x)); return y;
}
// two scalar f32 scores -> one f16x2 -> one MUFU for two exps
__device__ __forceinline__ u32 ex2h2s(float slo, float shi) {
    u32 h; asm("cvt.rn.f16x2.f32 %0, %1, %2;" : "=r"(h) : "f"(shi), "f"(slo));
    u32 e; asm("ex2.approx.f16x2 %0, %1;" : "=r"(e) : "r"(h));
    return e;
}

__global__ __launch_bounds__(128, 16) void rsca_kernel(
    const float* __restrict__ x, const float* __restrict__ y,
    const float* __restrict__ swq, const float* __restrict__ swk,
    const float* __restrict__ swv, const float* __restrict__ sbq,
    const float* __restrict__ sbk, const float* __restrict__ sbv,
    const float* __restrict__ swo, const float* __restrict__ sbo,
    float* __restrict__ out)
{
    const int n = blockIdx.x;
    const int i = threadIdx.x;

    __shared__ float4 xs[PASS_QUADS];  // 6656 B : 32-row staging window
    __shared__ float4 kv[B_DIM];       // 2 KB   : {kx, ky, vx, vy}
    __shared__ float4 wred[4];

    const float wq = *swq, wk = *swk, wv = *swv;
    const float bq = *sbq, bk = *sbk, bv = *sbv;
    const float wo = *swo, bo = *sbo;

    // ---- Pooling in FOUR passes of 32 rows (6.7 KB staging -> 16 blocks/SM) ----
    const int a = n & 3;
    const size_t baseq = ((size_t)n * HW - a) >> 2;       // float4 offset, exact
    const float4* g4 = (const float4*)x + baseq;

    float sum = 0.f;

    #pragma unroll
    for (int pass = 0; pass < 4; ++pass) {
        // cooperative coalesced load of rows [pass*32, pass*32+32)
        #pragma unroll
        for (int t = 0; t < 4; ++t) {
            int idx = i + t * B_DIM;
            if (idx < PASS_QUADS) {
                int r = idx / ROWQ, q = idx - r * ROWQ;
                xs[idx] = g4[(size_t)(r + pass * PASS_ROWS) * ROW_STRIDE_Q4 + q];
            }
        }
        __syncthreads();

        if ((i >> 5) == pass) {           // warp `pass` reduces its own rows
            const int li = i & 31;
            float4 q0 = xs[li * ROWQ + 0];
            float4 q12 = xs[li * ROWQ + 12];
            float s0 = q0.x + q0.y, s1 = q0.z + q0.w, s2 = 0.f, s3 = 0.f;
            #pragma unroll
            for (int t = 1; t < 12; t += 2) {
                float4 u = xs[li * ROWQ + t];
                float4 w = xs[li * ROWQ + t + 1];
                s0 += u.x; s1 += u.y; s2 += u.z; s3 += u.w;
                s0 += w.x; s1 += w.y; s2 += w.z; s3 += w.w;
            }
            sum = (s0 + s1) + (s2 + s3);   // w0..w51 each exactly once
            // valid window = [a, a+48]; remove the 3 invalid of the 52 loaded
            if (a >= 1) sum -= q0.x;  else sum -= q12.y;   // w0  vs w49
            if (a >= 2) sum -= q0.y;  else sum -= q12.z;   // w1  vs w50
            if (a >= 3) sum -= q0.z;  else sum -= q12.w;   // w2  vs w51
        }
        __syncthreads();
    }

    const float ax = sum * (1.0f / 49.0f);
    const float ay = y[(size_t)i * N_DIM + (size_t)n];

    // ---- projections (k pre-scaled by log2 e) ----
    const float L2E = 1.4426950408889634f;
    const float qx = fmaf(ax, wq, bq);
    const float qy = fmaf(ay, wq, bq);
    const float kx = fmaf(ax, wk, bk) * L2E;
    const float ky = fmaf(ay, wk, bk) * L2E;
    const float vx = fmaf(ax, wv, bv);
    const float vy = fmaf(ay, wv, bv);

    kv[i] = make_float4(kx, ky, vx, vy);

    // ---- block min/max of kx, ky (analytic per-row softmax max) ----
    float kxmx = kx, kxmn = kx, kymx = ky, kymn = ky;
    #pragma unroll
    for (int off = 16; off; off >>= 1) {
        kxmx = fmaxf(kxmx, __shfl_xor_sync(0xFFFFFFFFu, kxmx, off));
        kxmn = fminf(kxmn, __shfl_xor_sync(0xFFFFFFFFu, kxmn, off));
        kymx = fmaxf(kymx, __shfl_xor_sync(0xFFFFFFFFu, kymx, off));
        kymn = fminf(kymn, __shfl_xor_sync(0xFFFFFFFFu, kymn, off));
    }
    if ((i & 31) == 0) wred[i >> 5] = make_float4(kxmx, kxmn, kymx, kymn);
    __syncthreads();
    {
        float4 r0 = wred[0], r1 = wred[1], r2 = wred[2], r3 = wred[3];
        kxmx = fmaxf(fmaxf(r0.x, r1.x), fmaxf(r2.x, r3.x));
        kxmn = fminf(fminf(r0.y, r1.y), fminf(r2.y, r3.y));
        kymx = fmaxf(fmaxf(r0.z, r1.z), fmaxf(r2.z, r3.z));
        kymn = fminf(fminf(r0.w, r1.w), fminf(r2.w, r3.w));
    }

    const float nm1 = -((qx >= 0.f) ? qx * kxmx : qx * kxmn);  // self_x : qx,kx
    const float nm2 = -((qy >= 0.f) ? qy * kymx : qy * kymn);  // self_y : qy,ky
    const float nm3 = -((qx >= 0.f) ? qx * kymx : qx * kymn);  // cross_x: qx,ky
    const float nm4 = -((qy >= 0.f) ? qy * kxmx : qy * kxmn);  // cross_y: qy,kx

    // ---- fused 4-combo attention, scalar idiom, 3 MUFU/j ----
    // combos 1,2: exact scalar f32 MUFU. combos 4,3: one f16x2 MUFU.
    float d1 = 0.f, n1 = 0.f, d2 = 0.f, n2 = 0.f;
    u64 d43 = 0, n43 = 0;                 // packed {c4, c3} accumulators

    #pragma unroll 8
    for (int j = 0; j < B_DIM; ++j) {
        const float4 p = kv[j];           // {kx, ky, vx, vy} via broadcast LDS.128

        const float s1 = fmaf(qx, p.x, nm1);
        const float s2 = fmaf(qy, p.y, nm2);
        const float s4 = fmaf(qy, p.x, nm4);
        const float s3 = fmaf(qx, p.y, nm3);

        const float e1 = ex2f(s1);
        const float e2 = ex2f(s2);
        const u32 eh = ex2h2s(s4, s3);    // f16x2 {2^s4, 2^s3}

        // exact unpack, scaled 2^-112 (cancels in n/d); masks load-bearing
        const u32 lo = (eh << 13) & 0x0FFFE000u;
        const u32 hi = (eh >> 3)  & 0x0FFFE000u;
        const u64 f43 = pk2(__uint_as_float(lo), __uint_as_float(hi));

        d1 += e1; n1 = fmaf(e1, p.z, n1);
        d2 += e2; n2 = fmaf(e2, p.w, n2);
        const u64 vp = pk2(p.z, p.w);     // aligned pair from LDS.128
        d43 = add2(d43, f43);
        n43 = fma2(f43, vp, n43);          // n4+=e4*vx, n3+=e3*vy
    }

    float nn4, nn3, dd4, dd3;
    upk2(n43, nn4, nn3); upk2(d43, dd4, dd3);

    const float osx = __fdividef(n1, d1);
    const float osy = __fdividef(n2, d2);
    const float ocx = __fdividef(nn3, dd3);   // 2^-112 scale cancels
    const float ocy = __fdividef(nn4, dd4);

    const float ox = fmaf(wo, osx + ocx, ax + 2.0f * bo);
    const float oy = fmaf(wo, osy + ocy, ay + 2.0f * bo);

    out[(size_t)i * (2 * N_DIM) + (size_t)n]         = ox;
    out[(size_t)i * (2 * N_DIM) + N_DIM + (size_t)n] = oy;
}

extern "C" void kernel_launch(void* const* d_in, const int* in_sizes, int n_in,
                              void* d_out, int out_size) {
    const float* x   = (const float*)d_in[0];
    const float* y   = (const float*)d_in[1];
    const float* swq = (const float*)d_in[2];
    const float* swk = (const float*)d_in[3];
    const float* swv = (const float*)d_in[4];
    const float* sbq = (const float*)d_in[5];
    const float* sbk = (const float*)d_in[6];
    const float* sbv = (const float*)d_in[7];
    const float* swo = (const float*)d_in[8];
    const float* sbo = (const float*)d_in[9];
    float* out = (float*)d_out;

    rsca_kernel<<<N_DIM, B_DIM>>>(x, y, swq, swk, swv, sbq, sbk, sbv, swo, sbo, out);
}

// round 16
// speedup vs baseline: 1.2901x; 1.1244x over previous
#include <cuda_runtime.h>

#define B_DIM 128
#define N_DIM 8192
#define HW    49
#define ROWQ  13               // float4 quads per row window (52 floats)
#define PASS_ROWS 32
#define PASS_QUADS (PASS_ROWS * ROWQ)   // 416 quads staged per pass (6656 B)
#define ROW_STRIDE_Q4 100352   // 8192*49/4 : float4 stride between rows of x

__device__ __forceinline__ float ex2f(float x) {
    float y; asm("ex2.approx.ftz.f32 %0, %1;" : "=f"(y) : "f"(x)); return y;
}

__global__ __launch_bounds__(128, 16) void rsca_kernel(
    const float* __restrict__ x, const float* __restrict__ y,
    const float* __restrict__ swq, const float* __restrict__ swk,
    const float* __restrict__ swv, const float* __restrict__ sbq,
    const float* __restrict__ sbk, const float* __restrict__ sbv,
    const float* __restrict__ swo, const float* __restrict__ sbo,
    float* __restrict__ out)
{
    const int n = blockIdx.x;
    const int i = threadIdx.x;

    __shared__ float4 xs[PASS_QUADS];  // 6656 B : 32-row staging window
    __shared__ float4 kv[B_DIM];       // 2 KB   : {kx, ky, vx, vy}
    __shared__ float4 wred[4];

    const float wq = *swq, wk = *swk, wv = *swv;
    const float bq = *sbq, bk = *sbk, bv = *sbv;
    const float wo = *swo, bo = *sbo;

    // ---- Pooling in FOUR passes of 32 rows (cheap staged, high-occ) ----
    const int a = n & 3;
    const size_t baseq = ((size_t)n * HW - a) >> 2;       // float4 offset, exact
    const float4* g4 = (const float4*)x + baseq;

    float sum = 0.f;

    #pragma unroll
    for (int pass = 0; pass < 4; ++pass) {
        // cooperative coalesced load of rows [pass*32, pass*32+32)
        #pragma unroll
        for (int t = 0; t < 4; ++t) {
            int idx = i + t * B_DIM;
            if (idx < PASS_QUADS) {
                int r = idx / ROWQ, q = idx - r * ROWQ;
                xs[idx] = g4[(size_t)(r + pass * PASS_ROWS) * ROW_STRIDE_Q4 + q];
            }
        }
        __syncthreads();

        if ((i >> 5) == pass) {           // warp `pass` reduces its own rows
            const int li = i & 31;
            float4 q0 = xs[li * ROWQ + 0];
            float4 q12 = xs[li * ROWQ + 12];
            float s0 = q0.x + q0.y, s1 = q0.z + q0.w, s2 = 0.f, s3 = 0.f;
            #pragma unroll
            for (int t = 1; t < 12; t += 2) {
                float4 u = xs[li * ROWQ + t];
                float4 w = xs[li * ROWQ + t + 1];
                s0 += u.x; s1 += u.y; s2 += u.z; s3 += u.w;
                s0 += w.x; s1 += w.y; s2 += w.z; s3 += w.w;
            }
            sum = (s0 + s1) + (s2 + s3);   // w0..w51 each exactly once
            // valid window = [a, a+48]; remove the 3 invalid of the 52 loaded
            if (a >= 1) sum -= q0.x;  else sum -= q12.y;   // w0  vs w49
            if (a >= 2) sum -= q0.y;  else sum -= q12.z;   // w1  vs w50
            if (a >= 3) sum -= q0.z;  else sum -= q12.w;   // w2  vs w51
        }
        __syncthreads();
    }

    const float ax = sum * (1.0f / 49.0f);
    const float ay = y[(size_t)i * N_DIM + (size_t)n];

    // ---- projections (k pre-scaled by log2 e) ----
    const float L2E = 1.4426950408889634f;
    const float qx = fmaf(ax, wq, bq);
    const float qy = fmaf(ay, wq, bq);
    const float kx = fmaf(ax, wk, bk) * L2E;
    const float ky = fmaf(ay, wk, bk) * L2E;
    const float vx = fmaf(ax, wv, bv);
    const float vy = fmaf(ay, wv, bv);

    kv[i] = make_float4(kx, ky, vx, vy);

    // ---- block min/max of kx, ky (analytic per-row softmax max) ----
    float kxmx = kx, kxmn = kx, kymx = ky, kymn = ky;
    #pragma unroll
    for (int off = 16; off; off >>= 1) {
        kxmx = fmaxf(kxmx, __shfl_xor_sync(0xFFFFFFFFu, kxmx, off));
        kxmn = fminf(kxmn, __shfl_xor_sync(0xFFFFFFFFu, kxmn, off));
        kymx = fmaxf(kymx, __shfl_xor_sync(0xFFFFFFFFu, kymx, off));
        kymn = fminf(kymn, __shfl_xor_sync(0xFFFFFFFFu, kymn, off));
    }
    if ((i & 31) == 0) wred[i >> 5] = make_float4(kxmx, kxmn, kymx, kymn);
    __syncthreads();
    {
        float4 r0 = wred[0], r1 = wred[1], r2 = wred[2], r3 = wred[3];
        kxmx = fmaxf(fmaxf(r0.x, r1.x), fmaxf(r2.x, r3.x));
        kxmn = fminf(fminf(r0.y, r1.y), fminf(r2.y, r3.y));
        kymx = fmaxf(fmaxf(r0.z, r1.z), fmaxf(r2.z, r3.z));
        kymn = fminf(fminf(r0.w, r1.w), fminf(r2.w, r3.w));
    }

    const float nm1 = -((qx >= 0.f) ? qx * kxmx : qx * kxmn);  // self_x : qx,kx
    const float nm2 = -((qy >= 0.f) ? qy * kymx : qy * kymn);  // self_y : qy,ky
    const float nm3 = -((qx >= 0.f) ? qx * kymx : qx * kymn);  // cross_x: qx,ky
    const float nm4 = -((qy >= 0.f) ? qy * kxmx : qy * kxmn);  // cross_y: qy,kx

    // ---- fused 4-combo attention: PURE SCALAR, 4 f32 MUFU/j (the floor-achieving
    // idiom from R2: fma 24 cyc/j < MUFU 32 cyc/j, ~16 issues/j, no pack overhead) ----
    float n1 = 0.f, d1 = 0.f, n2 = 0.f, d2 = 0.f;
    float n3 = 0.f, d3 = 0.f, n4 = 0.f, d4 = 0.f;

    #pragma unroll 8
    for (int j = 0; j < B_DIM; ++j) {
        const float4 p = kv[j];           // {kx, ky, vx, vy} via broadcast LDS.128
        const float e1 = ex2f(fmaf(qx, p.x, nm1));
        const float e2 = ex2f(fmaf(qy, p.y, nm2));
        const float e3 = ex2f(fmaf(qx, p.y, nm3));
        const float e4 = ex2f(fmaf(qy, p.x, nm4));
        d1 += e1; n1 = fmaf(e1, p.z, n1);
        d2 += e2; n2 = fmaf(e2, p.w, n2);
        d3 += e3; n3 = fmaf(e3, p.w, n3);
        d4 += e4; n4 = fmaf(e4, p.z, n4);
    }

    const float osx = __fdividef(n1, d1);
    const float osy = __fdividef(n2, d2);
    const float ocx = __fdividef(n3, d3);
    const float ocy = __fdividef(n4, d4);

    const float ox = fmaf(wo, osx + ocx, ax + 2.0f * bo);
    const float oy = fmaf(wo, osy + ocy, ay + 2.0f * bo);

    out[(size_t)i * (2 * N_DIM) + (size_t)n]         = ox;
    out[(size_t)i * (2 * N_DIM) + N_DIM + (size_t)n] = oy;
}

extern "C" void kernel_launch(void* const* d_in, const int* in_sizes, int n_in,
                              void* d_out, int out_size) {
    const float* x   = (const float*)d_in[0];
    const float* y   = (const float*)d_in[1];
    const float* swq = (const float*)d_in[2];
    const float* swk = (const float*)d_in[3];
    const float* swv = (const float*)d_in[4];
    const float* sbq = (const float*)d_in[5];
    const float* sbk = (const float*)d_in[6];
    const float* sbv = (const float*)d_in[7];
    const float* swo = (const float*)d_in[8];
    const float* sbo = (const float*)d_in[9];
    float* out = (float*)d_out;

    rsca_kernel<<<N_DIM, B_DIM>>>(x, y, swq, swk, swv, sbq, sbk, sbv, swo, sbo, out);
}